// round 14
// baseline (speedup 1.0000x reference)
#include <cuda_runtime.h>
#include <cstdint>

#define BB 4
#define THW 3136
#define DEMO_TOK 784
#define OBS_TOK 2352
#define INV_TEMP 0.0625f
#define EPSV 1e-5f
#define CTHW (256*THW)

__device__ __align__(256) float g_x[BB*CTHW];
__device__ __align__(256) float g_dq[BB*256*DEMO_TOK];
__device__ __align__(256) float g_dk[BB*256*DEMO_TOK];
__device__ __align__(256) float g_dv[BB*256*DEMO_TOK];
__device__ __align__(256) float g_dvatt[BB*256*DEMO_TOK];
__device__ __align__(256) float g_oq[BB*256*OBS_TOK];
__device__ __align__(256) float g_ok[BB*256*OBS_TOK];
__device__ __align__(256) float g_ov[BB*256*OBS_TOK];
__device__ __align__(256) float g_mg[BB*256*OBS_TOK];
__device__ float g_mean[256];
__device__ float g_istd[256];

__device__ __forceinline__ unsigned long long pk2(float x) {
    unsigned long long r;
    asm("mov.b64 %0, {%1, %1};" : "=l"(r) : "f"(x));
    return r;
}
__device__ __forceinline__ unsigned long long fma2(
    unsigned long long a, unsigned long long b, unsigned long long c) {
    unsigned long long d;
    asm("fma.rn.f32x2 %0, %1, %2, %3;" : "=l"(d) : "l"(a), "l"(b), "l"(c));
    return d;
}
__device__ __forceinline__ float2 upk(unsigned long long v) {
    float2 f;
    asm("mov.b64 {%0, %1}, %2;" : "=f"(f.x), "=f"(f.y) : "l"(v));
    return f;
}

__device__ __forceinline__ void cp_async16(uint32_t dst, const void* src, int bytes) {
    asm volatile("cp.async.cg.shared.global [%0], [%1], 16, %2;\n"
                 :: "r"(dst), "l"(src), "r"(bytes));
}
__device__ __forceinline__ void cp_async4(uint32_t dst, const void* src, int srcsz) {
    asm volatile("cp.async.ca.shared.global [%0], [%1], 4, %2;\n"
                 :: "r"(dst), "l"(src), "r"(srcsz));
}
__device__ __forceinline__ void cp_commit() {
    asm volatile("cp.async.commit_group;\n");
}
template<int N> __device__ __forceinline__ void cp_wait() {
    asm volatile("cp.async.wait_group %0;\n" :: "n"(N));
}

__global__ void k_copy(const float4* __restrict__ src) {
    int e = blockIdx.x * 256 + threadIdx.x;
    ((float4*)g_x)[e] = src[e];
}

// ---------------- shared conv GEMM body (cp.async double-buffered, FFMA2) ----------------
__device__ __forceinline__ void conv_gemm(
    const float* __restrict__ W, const float* __restrict__ Xb,
    float* __restrict__ Ob, int ldx, int ldo, int N, int m0, int n0,
    int fuse, float* As, float* Bs, int t)
{
    const int ty = t >> 4, tx = t & 15;
    const int am = t >> 3, aq = t & 7;
    const int bk = t >> 4, bn = t & 15;
    const int ncol = n0 + bn * 4;
    const int bbytes = (ncol + 4 <= N) ? 16 : 0;
    const float* asrc0 = &W[(m0 + am) * 256 + aq * 4];
    const float* asrc1 = asrc0 + 32 * 256;
    const float* bsrc  = Xb + (long)bk * ldx + (bbytes ? ncol : n0);
    uint32_t asb = (uint32_t)__cvta_generic_to_shared(As);
    uint32_t bsb = (uint32_t)__cvta_generic_to_shared(Bs);
    const uint32_t ad0 = asb + (uint32_t)((am * 36 + aq * 4) * 4);
    const uint32_t ad1 = asb + (uint32_t)(((am + 32) * 36 + aq * 4) * 4);
    const uint32_t bd0 = bsb + (uint32_t)((bk * 64 + bn * 4) * 4);
    const uint32_t bd1 = bsb + (uint32_t)(((bk + 16) * 64 + bn * 4) * 4);
    const uint32_t ABUF = 64 * 36 * 4, BBUF = 32 * 64 * 4;

#define CPREF(K0, S) do { \
    cp_async16(ad0 + (S) * ABUF, asrc0 + (K0) * 32, 16); \
    cp_async16(ad1 + (S) * ABUF, asrc1 + (K0) * 32, 16); \
    cp_async16(bd0 + (S) * BBUF, bsrc + (long)((K0) * 32) * ldx, bbytes); \
    cp_async16(bd1 + (S) * BBUF, bsrc + (long)((K0) * 32 + 16) * ldx, bbytes); \
    cp_commit(); } while (0)

    unsigned long long acc2[4][2];
#pragma unroll
    for (int i = 0; i < 4; i++) { acc2[i][0] = 0ull; acc2[i][1] = 0ull; }

    CPREF(0, 0);
    for (int k0 = 0; k0 < 8; k0++) {
        const int cur = k0 & 1;
        if (k0 < 7) { CPREF(k0 + 1, cur ^ 1); cp_wait<1>(); }
        else        { cp_wait<0>(); }
        __syncthreads();
        const float* Ac = As + cur * (64 * 36);
        const float* Bc = Bs + cur * (32 * 64);
#pragma unroll
        for (int k4 = 0; k4 < 8; k4++) {
            float4 a4[4]; ulonglong2 b2[4];
#pragma unroll
            for (int i = 0; i < 4; i++)
                a4[i] = *(const float4*)&Ac[(ty * 4 + i) * 36 + k4 * 4];
#pragma unroll
            for (int kk = 0; kk < 4; kk++)
                b2[kk] = *(const ulonglong2*)&Bc[(k4 * 4 + kk) * 64 + tx * 4];
#pragma unroll
            for (int kk = 0; kk < 4; kk++) {
#pragma unroll
                for (int i = 0; i < 4; i++) {
                    float av = (kk == 0) ? a4[i].x : (kk == 1) ? a4[i].y
                             : (kk == 2) ? a4[i].z : a4[i].w;
                    unsigned long long aa = pk2(av);
                    acc2[i][0] = fma2(aa, b2[kk].x, acc2[i][0]);
                    acc2[i][1] = fma2(aa, b2[kk].y, acc2[i][1]);
                }
            }
        }
        __syncthreads();
    }
#undef CPREF

#pragma unroll
    for (int i = 0; i < 4; i++) {
        int m = m0 + ty * 4 + i;
        float2 p0 = upk(acc2[i][0]), p1 = upk(acc2[i][1]);
        float accf[4] = {p0.x, p0.y, p1.x, p1.y};
#pragma unroll
        for (int j = 0; j < 4; j++) {
            int n = n0 + tx * 4 + j;
            if (n < N) {
                float* p = Ob + (long)m * ldo + n;
                if (fuse) *p = *p + fmaxf(accf[j], 0.f);
                else      *p = accf[j];
            }
        }
    }
}

__global__ __launch_bounds__(256) void k_convD(
    const float* __restrict__ Wq, const float* __restrict__ Wk, const float* __restrict__ Wv)
{
    __shared__ float As[2][64*36];
    __shared__ float Bs[2][32*64];
    const int t = threadIdx.x, b = blockIdx.z, my = blockIdx.y;
    const int sel = my >> 2, m0 = (my & 3) * 64;
    const float* W = (sel == 0) ? Wq : ((sel == 1) ? Wk : Wv);
    const float* Xb = g_x + (long)b * CTHW;
    float* Ob = ((sel == 0) ? g_dq : (sel == 1) ? g_dk : g_dv) + (long)b * 256 * DEMO_TOK;
    conv_gemm(W, Xb, Ob, THW, DEMO_TOK, DEMO_TOK, m0, blockIdx.x * 64, 0,
              &As[0][0], &Bs[0][0], t);
}

__global__ __launch_bounds__(256) void k_convB(
    const float* __restrict__ Wq, const float* __restrict__ Wk, const float* __restrict__ Wv)
{
    __shared__ float As[2][64*36];
    __shared__ float Bs[2][32*64];
    const int t = threadIdx.x, b = blockIdx.z, my = blockIdx.y;
    const int sel = my >> 2, m0 = (my & 3) * 64;
    const float* W = (sel == 0) ? Wq : ((sel == 1) ? Wk : Wv);
    const float* Xb = g_x + (long)b * CTHW + DEMO_TOK;
    float* Ob = ((sel == 0) ? g_oq : (sel == 1) ? g_ok : g_ov) + (long)b * 256 * OBS_TOK;
    conv_gemm(W, Xb, Ob, THW, OBS_TOK, OBS_TOK, m0, blockIdx.x * 64, 0,
              &As[0][0], &Bs[0][0], t);
}

__global__ __launch_bounds__(256) void k_convO(const float* __restrict__ Wo)
{
    __shared__ float As[2][64*36];
    __shared__ float Bs[2][32*64];
    const int t = threadIdx.x, b = blockIdx.z;
    const float* Xb = g_mg + (long)b * 256 * OBS_TOK;
    float* Ob = g_x + (long)b * CTHW + DEMO_TOK;
    conv_gemm(Wo, Xb, Ob, OBS_TOK, THW, OBS_TOK, blockIdx.y * 64, blockIdx.x * 64, 1,
              &As[0][0], &Bs[0][0], t);
}

// ---------------- fused demo attention (round-12 passing version) ----------------
__global__ __launch_bounds__(256, 2) void k_demo_fused() {
    extern __shared__ float dyn[];       // 2 slots x 7488 floats
    __shared__ float Ks[512];
    __shared__ float Red[256];
    const int t = threadIdx.x;
    const int itile = blockIdx.x;
    const int bh = blockIdx.y;
    const int b = bh >> 3, h = bh & 7;
    const float* Kp = g_dk + ((long)b * 256 + h * 32) * DEMO_TOK;
    const float* Qp = g_dq + ((long)b * 256 + h * 32) * DEMO_TOK;
    const float* Vp = g_dv + ((long)b * 256 + h * 32) * DEMO_TOK;
    const uint32_t dsb = (uint32_t)__cvta_generic_to_shared(dyn);
    const int r = t & 15;
    const int g = t >> 4;
    const int wc = t >> 5;
    const int ln = t & 31;

#define PREF_Q(CB, S) do { \
    const float* qs_ = Qp + (long)((CB) * 8 + wc) * DEMO_TOK; \
    uint32_t qd_ = dsb + (uint32_t)(((S) * 7488 + wc * 832) * 4); \
    _Pragma("unroll") \
    for (int jq_ = 0; jq_ < 16; jq_++) { \
        _Pragma("unroll") \
        for (int hf_ = 0; hf_ < 2; hf_++) { \
            int jr_ = ln + hf_ * 32; \
            if (jr_ < 49) \
                cp_async4(qd_ + (uint32_t)((jq_ * 52 + jr_) * 4), qs_ + jq_ * 49 + jr_, 4); \
        } \
    } cp_commit(); } while (0)

#define PREF_V(TILE, S) do { \
    int jl_ = (TILE) * 13 + ln; \
    if (ln < 13 && jl_ < 49) { \
        _Pragma("unroll 16") \
        for (int it_ = 0; it_ < 64; it_++) { \
            int c_ = wc * 4 + (it_ >> 4); \
            int gg_ = it_ & 15; \
            cp_async4(dsb + (uint32_t)((((S) * 7488) + (gg_ * 13 + ln) * 36 + c_) * 4), \
                      Vp + (long)c_ * DEMO_TOK + gg_ * 49 + jl_, 4); \
        } \
    } cp_commit(); } while (0)

    unsigned long long acc2[24];
    float acc48 = 0.f;
#pragma unroll
    for (int p = 0; p < 24; p++) acc2[p] = 0ull;

#pragma unroll
    for (int e = t; e < 512; e += 256) {
        int c = e >> 4, ii = e & 15;
        Ks[c * 16 + ii] = Kp[(long)c * DEMO_TOK + itile * 16 + ii];
    }
    PREF_Q(0, 0);
    for (int cb = 0; cb < 4; cb++) {
        const int cur = cb & 1;
        if (cb < 3) PREF_Q(cb + 1, cur ^ 1);
        else        PREF_V(0, 0);
        cp_wait<1>();
        __syncthreads();
        const float* BigQ = dyn + cur * 7488;
#pragma unroll
        for (int cc = 0; cc < 8; cc++) {
            float a = Ks[(cb * 8 + cc) * 16 + r];
            unsigned long long aa = pk2(a);
            const ulonglong2* q2 = (const ulonglong2*)&BigQ[cc * 832 + g * 52];
#pragma unroll
            for (int v = 0; v < 12; v++) {
                ulonglong2 qq = q2[v];
                acc2[v*2+0] = fma2(aa, qq.x, acc2[v*2+0]);
                acc2[v*2+1] = fma2(aa, qq.y, acc2[v*2+1]);
            }
            acc48 += a * BigQ[cc * 832 + g * 52 + 48];
        }
        __syncthreads();
    }
    float acc[49];
#pragma unroll
    for (int p = 0; p < 24; p++) {
        float2 f = upk(acc2[p]);
        acc[p*2] = f.x; acc[p*2+1] = f.y;
    }
    acc[48] = acc48;
    float mx = -1e30f;
#pragma unroll
    for (int jj = 0; jj < 49; jj++) { acc[jj] *= INV_TEMP; mx = fmaxf(mx, acc[jj]); }
    Red[g * 16 + r] = mx;
    __syncthreads();
    float gm = Red[r];
#pragma unroll
    for (int gg = 1; gg < 16; gg++) gm = fmaxf(gm, Red[gg * 16 + r]);
    __syncthreads();
    float sm = 0.f;
#pragma unroll
    for (int jj = 0; jj < 49; jj++) { float p = __expf(acc[jj] - gm); acc[jj] = p; sm += p; }
    Red[g * 16 + r] = sm;
    __syncthreads();
    float gs = Red[r];
#pragma unroll
    for (int gg = 1; gg < 16; gg++) gs += Red[gg * 16 + r];
    float inv = 1.f / gs;
#pragma unroll
    for (int jj = 0; jj < 49; jj++) acc[jj] *= inv;

    unsigned long long pacc2[16];
#pragma unroll
    for (int p = 0; p < 16; p++) pacc2[p] = 0ull;
#pragma unroll
    for (int tile = 0; tile < 4; tile++) {
        const int vs = tile & 1;
        if (tile < 3) { PREF_V(tile + 1, vs ^ 1); cp_wait<1>(); }
        else          { cp_wait<0>(); }
        __syncthreads();
        const float* Vt = dyn + vs * 7488;
#pragma unroll
        for (int dj = 0; dj < 13; dj++) {
            const int jj = tile * 13 + dj;
            if (jj >= 49) break;
            unsigned long long pp = pk2(acc[jj]);
            const ulonglong2* vb2 = (const ulonglong2*)&Vt[(g * 13 + dj) * 36];
#pragma unroll
            for (int u = 0; u < 8; u++) {
                ulonglong2 v = vb2[u];
                pacc2[u*2+0] = fma2(v.x, pp, pacc2[u*2+0]);
                pacc2[u*2+1] = fma2(v.y, pp, pacc2[u*2+1]);
            }
        }
        __syncthreads();
    }
#undef PREF_Q
#undef PREF_V
    float pacc[32];
#pragma unroll
    for (int p = 0; p < 16; p++) {
        float2 f = upk(pacc2[p]);
        pacc[p*2] = f.x; pacc[p*2+1] = f.y;
    }
#pragma unroll
    for (int ch = 0; ch < 2; ch++) {
        __syncthreads();
#pragma unroll
        for (int cc = 0; cc < 16; cc++)
            dyn[t * 17 + cc] = pacc[ch * 16 + cc];
        __syncthreads();
        int rr = t >> 4, cc = t & 15;
        float s = 0.f;
#pragma unroll
        for (int gg = 0; gg < 16; gg++)
            s += dyn[(gg * 16 + rr) * 17 + cc];
        g_dvatt[((long)b * 256 + h * 32 + ch * 16 + cc) * DEMO_TOK + itile * 16 + rr] = s;
    }
}

// ---------------- fused obs attention: full 980 keys per block, j-pair AV ----------------
// smem: Ps[64][200] | Qs[32][208] | Kb[2][2048] | Vb[2][2304] = 112640 B
__global__ __launch_bounds__(256, 2) void k_obs_fused() {
    extern __shared__ float smem[];
    float* Ps = smem;
    float* Qs = smem + 12800;
    float* Kb = smem + 19456;
    float* Vb = smem + 23552;
    const int z = blockIdx.x;
    const int b = z / 96, tt = (z >> 3) % 12, h = z & 7;
    const int t = threadIdx.x;
    const float* Kd = g_dk    + ((long)b * 256 + h * 32) * DEMO_TOK;
    const float* Ko = g_ok    + ((long)b * 256 + h * 32) * OBS_TOK + tt * 196;
    const float* Vd = g_dvatt + ((long)b * 256 + h * 32) * DEMO_TOK;
    const float* Vo = g_ov    + ((long)b * 256 + h * 32) * OBS_TOK + tt * 196;
    const float* Qp = g_oq    + ((long)b * 256 + h * 32) * OBS_TOK + tt * 196;
    const uint32_t kbs = (uint32_t)__cvta_generic_to_shared(Kb);
    const uint32_t vbs = (uint32_t)__cvta_generic_to_shared(Vb);

    for (int e = t; e < 6272; e += 256) {
        int c = e / 196, j = e - c * 196;
        Qs[c * 208 + (j / 49) * 52 + (j % 49)] = Qp[(long)c * OBS_TOK + j];
    }

#define PREF_K(KT, S) do { \
    _Pragma("unroll") \
    for (int i_ = 0; i_ < 8; i_++) { \
        int e_ = i_ * 256 + t; \
        int c_ = e_ >> 6, ii_ = e_ & 63; \
        int kl_ = (KT) * 64 + ii_; \
        int sz_ = (kl_ < 980) ? 4 : 0; \
        int kg_ = (kl_ < 980) ? kl_ : 0; \
        const float* s_ = (kg_ < DEMO_TOK) ? (Kd + (long)c_ * DEMO_TOK + kg_) \
                                           : (Ko + (long)c_ * OBS_TOK + (kg_ - DEMO_TOK)); \
        cp_async4(kbs + (uint32_t)(((S) * 2048 + c_ * 64 + ii_) * 4), s_, sz_); \
    } cp_commit(); } while (0)

#define PREF_VO(KT, S) do { \
    _Pragma("unroll") \
    for (int i_ = 0; i_ < 8; i_++) { \
        int e_ = i_ * 256 + t; \
        int c_ = e_ >> 6, ii_ = e_ & 63; \
        int kl_ = (KT) * 64 + ii_; \
        int sz_ = (kl_ < 980) ? 4 : 0; \
        int kg_ = (kl_ < 980) ? kl_ : 0; \
        const float* s_ = (kg_ < DEMO_TOK) ? (Vd + (long)c_ * DEMO_TOK + kg_) \
                                           : (Vo + (long)c_ * OBS_TOK + (kg_ - DEMO_TOK)); \
        cp_async4(vbs + (uint32_t)(((S) * 2304 + ii_ * 36 + c_) * 4), s_, sz_); \
    } cp_commit(); } while (0)

    const int r = t >> 2, gq = t & 3;
    const int w = t >> 5, jg = t & 31;
    const bool tail = (jg < 2);
    unsigned long long out2[4][4];
#pragma unroll
    for (int c = 0; c < 4; c++)
#pragma unroll
        for (int p = 0; p < 4; p++) out2[c][p] = 0ull;

    PREF_K(0, 0);
    PREF_VO(0, 0);

    for (int kt = 0; kt < 16; kt++) {
        const int cur = kt & 1;
        if (kt < 15) { PREF_K(kt + 1, cur ^ 1); cp_wait<2>(); }
        else         { cp_wait<1>(); }
        __syncthreads();
        const float* Kc = Kb + cur * 2048;
        unsigned long long acc2[24];
        float acc48 = 0.f;
#pragma unroll
        for (int p = 0; p < 24; p++) acc2[p] = 0ull;
#pragma unroll
        for (int c = 0; c < 32; c++) {
            float a = Kc[c * 64 + r];
            unsigned long long aa = pk2(a);
            const ulonglong2* q2 = (const ulonglong2*)&Qs[c * 208 + gq * 52];
#pragma unroll
            for (int v = 0; v < 12; v++) {
                ulonglong2 qq = q2[v];
                acc2[v*2+0] = fma2(aa, qq.x, acc2[v*2+0]);
                acc2[v*2+1] = fma2(aa, qq.y, acc2[v*2+1]);
            }
            acc48 += a * Qs[c * 208 + gq * 52 + 48];
        }
        float acc[49];
#pragma unroll
        for (int p = 0; p < 24; p++) {
            float2 f = upk(acc2[p]);
            acc[p*2] = f.x; acc[p*2+1] = f.y;
        }
        acc[48] = acc48;
        float mx = -1e30f;
#pragma unroll
        for (int jj = 0; jj < 49; jj++) { acc[jj] *= INV_TEMP; mx = fmaxf(mx, acc[jj]); }
        mx = fmaxf(mx, __shfl_xor_sync(0xffffffffu, mx, 1));
        mx = fmaxf(mx, __shfl_xor_sync(0xffffffffu, mx, 2));
        float sm = 0.f;
#pragma unroll
        for (int jj = 0; jj < 49; jj++) { float p = __expf(acc[jj] - mx); acc[jj] = p; sm += p; }
        sm += __shfl_xor_sync(0xffffffffu, sm, 1);
        sm += __shfl_xor_sync(0xffffffffu, sm, 2);
        float inv = 1.f / sm;
        {
            float* pr = &Ps[r * 200 + gq * 49];
#pragma unroll
            for (int jj = 0; jj < 49; jj++) pr[jj] = acc[jj] * inv;
        }
        if (kt < 15) { PREF_VO(kt + 1, cur ^ 1); cp_wait<2>(); }
        else         { cp_wait<0>(); }
        __syncthreads();
        const float* Vc = Vb + cur * 2304;
#pragma unroll 4
        for (int k = 0; k < 64; k++) {
            ulonglong2 v2 = *(const ulonglong2*)&Vc[k * 36 + w * 4];
            float2 f01 = upk(v2.x), f23 = upk(v2.y);
            unsigned long long vb0 = pk2(f01.x), vb1 = pk2(f01.y);
            unsigned long long vb2w = pk2(f23.x), vb3 = pk2(f23.y);
            const float* pr = &Ps[k * 200];
            unsigned long long pp0 = *(const unsigned long long*)&pr[2 * jg];
            unsigned long long pp1 = *(const unsigned long long*)&pr[64 + 2 * jg];
            unsigned long long pp2 = *(const unsigned long long*)&pr[128 + 2 * jg];
            out2[0][0] = fma2(vb0, pp0, out2[0][0]);
            out2[1][0] = fma2(vb1, pp0, out2[1][0]);
            out2[2][0] = fma2(vb2w, pp0, out2[2][0]);
            out2[3][0] = fma2(vb3, pp0, out2[3][0]);
            out2[0][1] = fma2(vb0, pp1, out2[0][1]);
            out2[1][1] = fma2(vb1, pp1, out2[1][1]);
            out2[2][1] = fma2(vb2w, pp1, out2[2][1]);
            out2[3][1] = fma2(vb3, pp1, out2[3][1]);
            out2[0][2] = fma2(vb0, pp2, out2[0][2]);
            out2[1][2] = fma2(vb1, pp2, out2[1][2]);
            out2[2][2] = fma2(vb2w, pp2, out2[2][2]);
            out2[3][2] = fma2(vb3, pp2, out2[3][2]);
            if (tail) {
                unsigned long long pp3 = *(const unsigned long long*)&pr[192 + 2 * jg];
                out2[0][3] = fma2(vb0, pp3, out2[0][3]);
                out2[1][3] = fma2(vb1, pp3, out2[1][3]);
                out2[2][3] = fma2(vb2w, pp3, out2[2][3]);
                out2[3][3] = fma2(vb3, pp3, out2[3][3]);
            }
        }
    }
#undef PREF_K
#undef PREF_VO
    float* op = g_mg + ((long)b * 256 + h * 32) * OBS_TOK + tt * 196;
#pragma unroll
    for (int c = 0; c < 4; c++) {
        long cb = (long)(w * 4 + c) * OBS_TOK;
#pragma unroll
        for (int p = 0; p < 3; p++) {
            float2 f = upk(out2[c][p]);
            *(float2*)&op[cb + p * 64 + 2 * jg] = f;
        }
        if (tail) {
            float2 f = upk(out2[c][3]);
            *(float2*)&op[cb + 192 + 2 * jg] = f;
        }
    }
}

__global__ void k_bnstats() {
    const int c = blockIdx.x;
    float s = 0.f, s2 = 0.f;
    for (int e = threadIdx.x; e < BB * THW; e += 256) {
        int b = e / THW, k = e - b * THW;
        float v = g_x[(long)b * CTHW + (long)c * THW + k];
        s += v; s2 += v * v;
    }
#pragma unroll
    for (int o = 16; o; o >>= 1) {
        s  += __shfl_xor_sync(0xffffffffu, s, o);
        s2 += __shfl_xor_sync(0xffffffffu, s2, o);
    }
    __shared__ float ws[8], ws2[8];
    int w = threadIdx.x >> 5;
    if ((threadIdx.x & 31) == 0) { ws[w] = s; ws2[w] = s2; }
    __syncthreads();
    if (threadIdx.x == 0) {
        float S = 0.f, S2 = 0.f;
#pragma unroll
        for (int i = 0; i < 8; i++) { S += ws[i]; S2 += ws2[i]; }
        float m = S * (1.f / 12544.f);
        float var = S2 * (1.f / 12544.f) - m * m;
        g_mean[c] = m;
        g_istd[c] = rsqrtf(var + EPSV);
    }
}

__global__ void k_bnapply(const float* __restrict__ gamma, const float* __restrict__ beta,
                          float* __restrict__ out) {
    int e = blockIdx.x * 256 + threadIdx.x;
    int c = (e / 784) & 255;
    float4 v = ((const float4*)g_x)[e];
    float a = gamma[c] * g_istd[c];
    float b2 = beta[c] - g_mean[c] * a;
    v.x = v.x * a + b2; v.y = v.y * a + b2; v.z = v.z * a + b2; v.w = v.w * a + b2;
    ((float4*)out)[e] = v;
}

extern "C" void kernel_launch(void* const* d_in, const int* in_sizes, int n_in,
                              void* d_out, int out_size) {
    const float* x    = (const float*)d_in[0];
    const float* w_dq = (const float*)d_in[1];
    const float* w_dk = (const float*)d_in[2];
    const float* w_dv = (const float*)d_in[3];
    const float* w_oq = (const float*)d_in[4];
    const float* w_ok = (const float*)d_in[5];
    const float* w_ov = (const float*)d_in[6];
    const float* w_oo = (const float*)d_in[7];
    const float* gam  = (const float*)d_in[8];
    const float* bet  = (const float*)d_in[9];
    float* out = (float*)d_out;

    float* p_x;
    cudaGetSymbolAddress((void**)&p_x, g_x);

    cudaFuncSetAttribute(k_obs_fused, cudaFuncAttributeMaxDynamicSharedMemorySize, 112640);
    cudaFuncSetAttribute(k_demo_fused, cudaFuncAttributeMaxDynamicSharedMemorySize, 59904);

    k_copy<<<3136, 256>>>((const float4*)x);

    for (int l = 0; l < 3; l++) {
        const int WO = l * 256 * 256;
        k_convD<<<dim3(13, 12, BB), 256>>>(w_dq + WO, w_dk + WO, w_dv + WO);
        k_convB<<<dim3(37, 12, BB), 256>>>(w_oq + WO, w_ok + WO, w_ov + WO);
        k_demo_fused<<<dim3(49, 32), 256, 59904>>>();
        k_obs_fused<<<384, 256, 112640>>>();
        k_convO<<<dim3(37, 4, BB), 256>>>(w_oo + WO);
        k_bnstats<<<256, 256>>>();
        k_bnapply<<<3136, 256>>>(gam + l * 256, bet + l * 256, (l == 2) ? out : p_x);
    }
}

// round 15
// speedup vs baseline: 1.0178x; 1.0178x over previous
#include <cuda_runtime.h>
#include <cstdint>

#define BB 4
#define THW 3136
#define DEMO_TOK 784
#define OBS_TOK 2352
#define INV_TEMP 0.0625f
#define EPSV 1e-5f
#define CTHW (256*THW)

__device__ __align__(256) float g_x[BB*CTHW];
__device__ __align__(256) float g_dq[BB*256*DEMO_TOK];
__device__ __align__(256) float g_dk[BB*256*DEMO_TOK];
__device__ __align__(256) float g_dv[BB*256*DEMO_TOK];
__device__ __align__(256) float g_dvatt[BB*256*DEMO_TOK];
__device__ __align__(256) float g_oq[BB*256*OBS_TOK];
__device__ __align__(256) float g_ok[BB*256*OBS_TOK];
__device__ __align__(256) float g_ov[BB*256*OBS_TOK];
__device__ __align__(256) float g_mg[BB*256*OBS_TOK];
__device__ __align__(256) float g_part[2*384*32*196];
__device__ float g_mean[256];
__device__ float g_istd[256];

__device__ __forceinline__ unsigned long long pk2(float x) {
    unsigned long long r;
    asm("mov.b64 %0, {%1, %1};" : "=l"(r) : "f"(x));
    return r;
}
__device__ __forceinline__ unsigned long long fma2(
    unsigned long long a, unsigned long long b, unsigned long long c) {
    unsigned long long d;
    asm("fma.rn.f32x2 %0, %1, %2, %3;" : "=l"(d) : "l"(a), "l"(b), "l"(c));
    return d;
}
__device__ __forceinline__ float2 upk(unsigned long long v) {
    float2 f;
    asm("mov.b64 {%0, %1}, %2;" : "=f"(f.x), "=f"(f.y) : "l"(v));
    return f;
}

__device__ __forceinline__ void cp_async16(uint32_t dst, const void* src, int bytes) {
    asm volatile("cp.async.cg.shared.global [%0], [%1], 16, %2;\n"
                 :: "r"(dst), "l"(src), "r"(bytes));
}
__device__ __forceinline__ void cp_async4(uint32_t dst, const void* src, int srcsz) {
    asm volatile("cp.async.ca.shared.global [%0], [%1], 4, %2;\n"
                 :: "r"(dst), "l"(src), "r"(srcsz));
}
__device__ __forceinline__ void cp_commit() {
    asm volatile("cp.async.commit_group;\n");
}
template<int N> __device__ __forceinline__ void cp_wait() {
    asm volatile("cp.async.wait_group %0;\n" :: "n"(N));
}

__global__ void k_copy(const float4* __restrict__ src) {
    int e = blockIdx.x * 256 + threadIdx.x;
    ((float4*)g_x)[e] = src[e];
}

// ---------------- shared conv GEMM body (cp.async double-buffered, FFMA2) ----------------
__device__ __forceinline__ void conv_gemm(
    const float* __restrict__ W, const float* __restrict__ Xb,
    float* __restrict__ Ob, int ldx, int ldo, int N, int m0, int n0,
    int fuse, float* As, float* Bs, int t)
{
    const int ty = t >> 4, tx = t & 15;
    const int am = t >> 3, aq = t & 7;
    const int bk = t >> 4, bn = t & 15;
    const int ncol = n0 + bn * 4;
    const int bbytes = (ncol + 4 <= N) ? 16 : 0;
    const float* asrc0 = &W[(m0 + am) * 256 + aq * 4];
    const float* asrc1 = asrc0 + 32 * 256;
    const float* bsrc  = Xb + (long)bk * ldx + (bbytes ? ncol : n0);
    uint32_t asb = (uint32_t)__cvta_generic_to_shared(As);
    uint32_t bsb = (uint32_t)__cvta_generic_to_shared(Bs);
    const uint32_t ad0 = asb + (uint32_t)((am * 36 + aq * 4) * 4);
    const uint32_t ad1 = asb + (uint32_t)(((am + 32) * 36 + aq * 4) * 4);
    const uint32_t bd0 = bsb + (uint32_t)((bk * 64 + bn * 4) * 4);
    const uint32_t bd1 = bsb + (uint32_t)(((bk + 16) * 64 + bn * 4) * 4);
    const uint32_t ABUF = 64 * 36 * 4, BBUF = 32 * 64 * 4;

#define CPREF(K0, S) do { \
    cp_async16(ad0 + (S) * ABUF, asrc0 + (K0) * 32, 16); \
    cp_async16(ad1 + (S) * ABUF, asrc1 + (K0) * 32, 16); \
    cp_async16(bd0 + (S) * BBUF, bsrc + (long)((K0) * 32) * ldx, bbytes); \
    cp_async16(bd1 + (S) * BBUF, bsrc + (long)((K0) * 32 + 16) * ldx, bbytes); \
    cp_commit(); } while (0)

    unsigned long long acc2[4][2];
#pragma unroll
    for (int i = 0; i < 4; i++) { acc2[i][0] = 0ull; acc2[i][1] = 0ull; }

    CPREF(0, 0);
    for (int k0 = 0; k0 < 8; k0++) {
        const int cur = k0 & 1;
        if (k0 < 7) { CPREF(k0 + 1, cur ^ 1); cp_wait<1>(); }
        else        { cp_wait<0>(); }
        __syncthreads();
        const float* Ac = As + cur * (64 * 36);
        const float* Bc = Bs + cur * (32 * 64);
#pragma unroll
        for (int k4 = 0; k4 < 8; k4++) {
            float4 a4[4]; ulonglong2 b2[4];
#pragma unroll
            for (int i = 0; i < 4; i++)
                a4[i] = *(const float4*)&Ac[(ty * 4 + i) * 36 + k4 * 4];
#pragma unroll
            for (int kk = 0; kk < 4; kk++)
                b2[kk] = *(const ulonglong2*)&Bc[(k4 * 4 + kk) * 64 + tx * 4];
#pragma unroll
            for (int kk = 0; kk < 4; kk++) {
#pragma unroll
                for (int i = 0; i < 4; i++) {
                    float av = (kk == 0) ? a4[i].x : (kk == 1) ? a4[i].y
                             : (kk == 2) ? a4[i].z : a4[i].w;
                    unsigned long long aa = pk2(av);
                    acc2[i][0] = fma2(aa, b2[kk].x, acc2[i][0]);
                    acc2[i][1] = fma2(aa, b2[kk].y, acc2[i][1]);
                }
            }
        }
        __syncthreads();
    }
#undef CPREF

#pragma unroll
    for (int i = 0; i < 4; i++) {
        int m = m0 + ty * 4 + i;
        float2 p0 = upk(acc2[i][0]), p1 = upk(acc2[i][1]);
        float accf[4] = {p0.x, p0.y, p1.x, p1.y};
#pragma unroll
        for (int j = 0; j < 4; j++) {
            int n = n0 + tx * 4 + j;
            if (n < N) {
                float* p = Ob + (long)m * ldo + n;
                if (fuse) *p = *p + fmaxf(accf[j], 0.f);
                else      *p = accf[j];
            }
        }
    }
}

__global__ __launch_bounds__(256) void k_convD(
    const float* __restrict__ Wq, const float* __restrict__ Wk, const float* __restrict__ Wv)
{
    __shared__ float As[2][64*36];
    __shared__ float Bs[2][32*64];
    const int t = threadIdx.x, b = blockIdx.z, my = blockIdx.y;
    const int sel = my >> 2, m0 = (my & 3) * 64;
    const float* W = (sel == 0) ? Wq : ((sel == 1) ? Wk : Wv);
    const float* Xb = g_x + (long)b * CTHW;
    float* Ob = ((sel == 0) ? g_dq : (sel == 1) ? g_dk : g_dv) + (long)b * 256 * DEMO_TOK;
    conv_gemm(W, Xb, Ob, THW, DEMO_TOK, DEMO_TOK, m0, blockIdx.x * 64, 0,
              &As[0][0], &Bs[0][0], t);
}

__global__ __launch_bounds__(256) void k_convB(
    const float* __restrict__ Wq, const float* __restrict__ Wk, const float* __restrict__ Wv)
{
    __shared__ float As[2][64*36];
    __shared__ float Bs[2][32*64];
    const int t = threadIdx.x, b = blockIdx.z, my = blockIdx.y;
    const int sel = my >> 2, m0 = (my & 3) * 64;
    const float* W = (sel == 0) ? Wq : ((sel == 1) ? Wk : Wv);
    const float* Xb = g_x + (long)b * CTHW + DEMO_TOK;
    float* Ob = ((sel == 0) ? g_oq : (sel == 1) ? g_ok : g_ov) + (long)b * 256 * OBS_TOK;
    conv_gemm(W, Xb, Ob, THW, OBS_TOK, OBS_TOK, m0, blockIdx.x * 64, 0,
              &As[0][0], &Bs[0][0], t);
}

__global__ __launch_bounds__(256) void k_convO(const float* __restrict__ Wo)
{
    __shared__ float As[2][64*36];
    __shared__ float Bs[2][32*64];
    const int t = threadIdx.x, b = blockIdx.z;
    const float* Xb = g_mg + (long)b * 256 * OBS_TOK;
    float* Ob = g_x + (long)b * CTHW + DEMO_TOK;
    conv_gemm(Wo, Xb, Ob, OBS_TOK, THW, OBS_TOK, blockIdx.y * 64, blockIdx.x * 64, 1,
              &As[0][0], &Bs[0][0], t);
}

// ---------------- fused demo attention (round-12 passing version) ----------------
__global__ __launch_bounds__(256, 2) void k_demo_fused() {
    extern __shared__ float dyn[];       // 2 slots x 7488 floats
    __shared__ float Ks[512];
    __shared__ float Red[256];
    const int t = threadIdx.x;
    const int itile = blockIdx.x;
    const int bh = blockIdx.y;
    const int b = bh >> 3, h = bh & 7;
    const float* Kp = g_dk + ((long)b * 256 + h * 32) * DEMO_TOK;
    const float* Qp = g_dq + ((long)b * 256 + h * 32) * DEMO_TOK;
    const float* Vp = g_dv + ((long)b * 256 + h * 32) * DEMO_TOK;
    const uint32_t dsb = (uint32_t)__cvta_generic_to_shared(dyn);
    const int r = t & 15;
    const int g = t >> 4;
    const int wc = t >> 5;
    const int ln = t & 31;

#define PREF_Q(CB, S) do { \
    const float* qs_ = Qp + (long)((CB) * 8 + wc) * DEMO_TOK; \
    uint32_t qd_ = dsb + (uint32_t)(((S) * 7488 + wc * 832) * 4); \
    _Pragma("unroll") \
    for (int jq_ = 0; jq_ < 16; jq_++) { \
        _Pragma("unroll") \
        for (int hf_ = 0; hf_ < 2; hf_++) { \
            int jr_ = ln + hf_ * 32; \
            if (jr_ < 49) \
                cp_async4(qd_ + (uint32_t)((jq_ * 52 + jr_) * 4), qs_ + jq_ * 49 + jr_, 4); \
        } \
    } cp_commit(); } while (0)

#define PREF_V(TILE, S) do { \
    int jl_ = (TILE) * 13 + ln; \
    if (ln < 13 && jl_ < 49) { \
        _Pragma("unroll 16") \
        for (int it_ = 0; it_ < 64; it_++) { \
            int c_ = wc * 4 + (it_ >> 4); \
            int gg_ = it_ & 15; \
            cp_async4(dsb + (uint32_t)((((S) * 7488) + (gg_ * 13 + ln) * 36 + c_) * 4), \
                      Vp + (long)c_ * DEMO_TOK + gg_ * 49 + jl_, 4); \
        } \
    } cp_commit(); } while (0)

    unsigned long long acc2[24];
    float acc48 = 0.f;
#pragma unroll
    for (int p = 0; p < 24; p++) acc2[p] = 0ull;

#pragma unroll
    for (int e = t; e < 512; e += 256) {
        int c = e >> 4, ii = e & 15;
        Ks[c * 16 + ii] = Kp[(long)c * DEMO_TOK + itile * 16 + ii];
    }
    PREF_Q(0, 0);
    for (int cb = 0; cb < 4; cb++) {
        const int cur = cb & 1;
        if (cb < 3) PREF_Q(cb + 1, cur ^ 1);
        else        PREF_V(0, 0);
        cp_wait<1>();
        __syncthreads();
        const float* BigQ = dyn + cur * 7488;
#pragma unroll
        for (int cc = 0; cc < 8; cc++) {
            float a = Ks[(cb * 8 + cc) * 16 + r];
            unsigned long long aa = pk2(a);
            const ulonglong2* q2 = (const ulonglong2*)&BigQ[cc * 832 + g * 52];
#pragma unroll
            for (int v = 0; v < 12; v++) {
                ulonglong2 qq = q2[v];
                acc2[v*2+0] = fma2(aa, qq.x, acc2[v*2+0]);
                acc2[v*2+1] = fma2(aa, qq.y, acc2[v*2+1]);
            }
            acc48 += a * BigQ[cc * 832 + g * 52 + 48];
        }
        __syncthreads();
    }
    float acc[49];
#pragma unroll
    for (int p = 0; p < 24; p++) {
        float2 f = upk(acc2[p]);
        acc[p*2] = f.x; acc[p*2+1] = f.y;
    }
    acc[48] = acc48;
    float mx = -1e30f;
#pragma unroll
    for (int jj = 0; jj < 49; jj++) { acc[jj] *= INV_TEMP; mx = fmaxf(mx, acc[jj]); }
    Red[g * 16 + r] = mx;
    __syncthreads();
    float gm = Red[r];
#pragma unroll
    for (int gg = 1; gg < 16; gg++) gm = fmaxf(gm, Red[gg * 16 + r]);
    __syncthreads();
    float sm = 0.f;
#pragma unroll
    for (int jj = 0; jj < 49; jj++) { float p = __expf(acc[jj] - gm); acc[jj] = p; sm += p; }
    Red[g * 16 + r] = sm;
    __syncthreads();
    float gs = Red[r];
#pragma unroll
    for (int gg = 1; gg < 16; gg++) gs += Red[gg * 16 + r];
    float inv = 1.f / gs;
#pragma unroll
    for (int jj = 0; jj < 49; jj++) acc[jj] *= inv;

    unsigned long long pacc2[16];
#pragma unroll
    for (int p = 0; p < 16; p++) pacc2[p] = 0ull;
#pragma unroll
    for (int tile = 0; tile < 4; tile++) {
        const int vs = tile & 1;
        if (tile < 3) { PREF_V(tile + 1, vs ^ 1); cp_wait<1>(); }
        else          { cp_wait<0>(); }
        __syncthreads();
        const float* Vt = dyn + vs * 7488;
#pragma unroll
        for (int dj = 0; dj < 13; dj++) {
            const int jj = tile * 13 + dj;
            if (jj >= 49) break;
            unsigned long long pp = pk2(acc[jj]);
            const ulonglong2* vb2 = (const ulonglong2*)&Vt[(g * 13 + dj) * 36];
#pragma unroll
            for (int u = 0; u < 8; u++) {
                ulonglong2 v = vb2[u];
                pacc2[u*2+0] = fma2(v.x, pp, pacc2[u*2+0]);
                pacc2[u*2+1] = fma2(v.y, pp, pacc2[u*2+1]);
            }
        }
        __syncthreads();
    }
#undef PREF_Q
#undef PREF_V
    float pacc[32];
#pragma unroll
    for (int p = 0; p < 16; p++) {
        float2 f = upk(pacc2[p]);
        pacc[p*2] = f.x; pacc[p*2+1] = f.y;
    }
#pragma unroll
    for (int ch = 0; ch < 2; ch++) {
        __syncthreads();
#pragma unroll
        for (int cc = 0; cc < 16; cc++)
            dyn[t * 17 + cc] = pacc[ch * 16 + cc];
        __syncthreads();
        int rr = t >> 4, cc = t & 15;
        float s = 0.f;
#pragma unroll
        for (int gg = 0; gg < 16; gg++)
            s += dyn[(gg * 16 + rr) * 17 + cc];
        g_dvatt[((long)b * 256 + h * 32 + ch * 16 + cc) * DEMO_TOK + itile * 16 + rr] = s;
    }
}

// ---------------- fused obs attention: khalf split (768 blocks) + j-pair AV ----------------
// smem: Ps[64][200] | Qs[32][208] | Kb[2][2048] | Vb[2][2304] = 112640 B
__global__ __launch_bounds__(256, 2) void k_obs_fused(float* __restrict__ part) {
    extern __shared__ float smem[];
    float* Ps = smem;
    float* Qs = smem + 12800;
    float* Kb = smem + 19456;
    float* Vb = smem + 23552;
    const int z = blockIdx.x;
    const int khalf = blockIdx.y;
    const int b = z / 96, tt = (z >> 3) % 12, h = z & 7;
    const int t = threadIdx.x;
    const float* Kd = g_dk    + ((long)b * 256 + h * 32) * DEMO_TOK;
    const float* Ko = g_ok    + ((long)b * 256 + h * 32) * OBS_TOK + tt * 196;
    const float* Vd = g_dvatt + ((long)b * 256 + h * 32) * DEMO_TOK;
    const float* Vo = g_ov    + ((long)b * 256 + h * 32) * OBS_TOK + tt * 196;
    const float* Qp = g_oq    + ((long)b * 256 + h * 32) * OBS_TOK + tt * 196;
    const uint32_t kbs = (uint32_t)__cvta_generic_to_shared(Kb);
    const uint32_t vbs = (uint32_t)__cvta_generic_to_shared(Vb);
    const int kbase = khalf * 490;

    for (int e = t; e < 6272; e += 256) {
        int c = e / 196, j = e - c * 196;
        Qs[c * 208 + (j / 49) * 52 + (j % 49)] = Qp[(long)c * OBS_TOK + j];
    }

#define PREF_K(KT, S) do { \
    _Pragma("unroll") \
    for (int i_ = 0; i_ < 8; i_++) { \
        int e_ = i_ * 256 + t; \
        int c_ = e_ >> 6, ii_ = e_ & 63; \
        int kl_ = (KT) * 64 + ii_; \
        int sz_ = (kl_ < 490) ? 4 : 0; \
        int kg_ = kbase + ((kl_ < 490) ? kl_ : 0); \
        const float* s_ = (kg_ < DEMO_TOK) ? (Kd + (long)c_ * DEMO_TOK + kg_) \
                                           : (Ko + (long)c_ * OBS_TOK + (kg_ - DEMO_TOK)); \
        cp_async4(kbs + (uint32_t)(((S) * 2048 + c_ * 64 + ii_) * 4), s_, sz_); \
    } cp_commit(); } while (0)

#define PREF_VO(KT, S) do { \
    _Pragma("unroll") \
    for (int i_ = 0; i_ < 8; i_++) { \
        int e_ = i_ * 256 + t; \
        int c_ = e_ >> 6, ii_ = e_ & 63; \
        int kl_ = (KT) * 64 + ii_; \
        int sz_ = (kl_ < 490) ? 4 : 0; \
        int kg_ = kbase + ((kl_ < 490) ? kl_ : 0); \
        const float* s_ = (kg_ < DEMO_TOK) ? (Vd + (long)c_ * DEMO_TOK + kg_) \
                                           : (Vo + (long)c_ * OBS_TOK + (kg_ - DEMO_TOK)); \
        cp_async4(vbs + (uint32_t)(((S) * 2304 + ii_ * 36 + c_) * 4), s_, sz_); \
    } cp_commit(); } while (0)

    const int r = t >> 2, gq = t & 3;
    const int w = t >> 5, jg = t & 31;
    const bool tail = (jg < 2);
    unsigned long long out2[4][4];
#pragma unroll
    for (int c = 0; c < 4; c++)
#pragma unroll
        for (int p = 0; p < 4; p++) out2[c][p] = 0ull;

    PREF_K(0, 0);
    PREF_VO(0, 0);

    for (int kt = 0; kt < 8; kt++) {
        const int cur = kt & 1;
        if (kt < 7) { PREF_K(kt + 1, cur ^ 1); cp_wait<2>(); }
        else        { cp_wait<1>(); }
        __syncthreads();
        const float* Kc = Kb + cur * 2048;
        unsigned long long acc2[24];
        float acc48 = 0.f;
#pragma unroll
        for (int p = 0; p < 24; p++) acc2[p] = 0ull;
#pragma unroll
        for (int c = 0; c < 32; c++) {
            float a = Kc[c * 64 + r];
            unsigned long long aa = pk2(a);
            const ulonglong2* q2 = (const ulonglong2*)&Qs[c * 208 + gq * 52];
#pragma unroll
            for (int v = 0; v < 12; v++) {
                ulonglong2 qq = q2[v];
                acc2[v*2+0] = fma2(aa, qq.x, acc2[v*2+0]);
                acc2[v*2+1] = fma2(aa, qq.y, acc2[v*2+1]);
            }
            acc48 += a * Qs[c * 208 + gq * 52 + 48];
        }
        float acc[49];
#pragma unroll
        for (int p = 0; p < 24; p++) {
            float2 f = upk(acc2[p]);
            acc[p*2] = f.x; acc[p*2+1] = f.y;
        }
        acc[48] = acc48;
        float mx = -1e30f;
#pragma unroll
        for (int jj = 0; jj < 49; jj++) { acc[jj] *= INV_TEMP; mx = fmaxf(mx, acc[jj]); }
        mx = fmaxf(mx, __shfl_xor_sync(0xffffffffu, mx, 1));
        mx = fmaxf(mx, __shfl_xor_sync(0xffffffffu, mx, 2));
        float sm = 0.f;
#pragma unroll
        for (int jj = 0; jj < 49; jj++) { float p = __expf(acc[jj] - mx); acc[jj] = p; sm += p; }
        sm += __shfl_xor_sync(0xffffffffu, sm, 1);
        sm += __shfl_xor_sync(0xffffffffu, sm, 2);
        float inv = 1.f / sm;
        {
            float* pr = &Ps[r * 200 + gq * 49];
#pragma unroll
            for (int jj = 0; jj < 49; jj++) pr[jj] = acc[jj] * inv;
        }
        if (kt < 7) { PREF_VO(kt + 1, cur ^ 1); cp_wait<2>(); }
        else        { cp_wait<0>(); }
        __syncthreads();
        const float* Vc = Vb + cur * 2304;
        // AV: j-pair packed P operands (LDS.64), per-channel V broadcast
#pragma unroll 4
        for (int k = 0; k < 64; k++) {
            ulonglong2 v2 = *(const ulonglong2*)&Vc[k * 36 + w * 4];
            float2 f01 = upk(v2.x), f23 = upk(v2.y);
            unsigned long long vb0 = pk2(f01.x), vb1 = pk2(f01.y);
            unsigned long long vb2w = pk2(f23.x), vb3 = pk2(f23.y);
            const float* pr = &Ps[k * 200];
            unsigned long long pp0 = *(const unsigned long long*)&pr[2 * jg];
            unsigned long long pp1 = *(const unsigned long long*)&pr[64 + 2 * jg];
            unsigned long long pp2 = *(const unsigned long long*)&pr[128 + 2 * jg];
            out2[0][0] = fma2(vb0, pp0, out2[0][0]);
            out2[1][0] = fma2(vb1, pp0, out2[1][0]);
            out2[2][0] = fma2(vb2w, pp0, out2[2][0]);
            out2[3][0] = fma2(vb3, pp0, out2[3][0]);
            out2[0][1] = fma2(vb0, pp1, out2[0][1]);
            out2[1][1] = fma2(vb1, pp1, out2[1][1]);
            out2[2][1] = fma2(vb2w, pp1, out2[2][1]);
            out2[3][1] = fma2(vb3, pp1, out2[3][1]);
            out2[0][2] = fma2(vb0, pp2, out2[0][2]);
            out2[1][2] = fma2(vb1, pp2, out2[1][2]);
            out2[2][2] = fma2(vb2w, pp2, out2[2][2]);
            out2[3][2] = fma2(vb3, pp2, out2[3][2]);
            if (tail) {
                unsigned long long pp3 = *(const unsigned long long*)&pr[192 + 2 * jg];
                out2[0][3] = fma2(vb0, pp3, out2[0][3]);
                out2[1][3] = fma2(vb1, pp3, out2[1][3]);
                out2[2][3] = fma2(vb2w, pp3, out2[2][3]);
                out2[3][3] = fma2(vb3, pp3, out2[3][3]);
            }
        }
    }
#undef PREF_K
#undef PREF_VO
    // writeback partials (float2 stores)
    float* op = part + ((long)(khalf * 384 + z)) * 6272;
#pragma unroll
    for (int c = 0; c < 4; c++) {
        int cb = (w * 4 + c) * 196;
#pragma unroll
        for (int p = 0; p < 3; p++) {
            float2 f = upk(out2[c][p]);
            *(float2*)&op[cb + p * 64 + 2 * jg] = f;
        }
        if (tail) {
            float2 f = upk(out2[c][3]);
            *(float2*)&op[cb + 192 + 2 * jg] = f;
        }
    }
}

// ---------------- merge obs AV partials into g_mg (conv layout) ----------------
__global__ void k_merge(const float* __restrict__ part) {
    int z = blockIdx.y;
    int e = blockIdx.x * 256 + threadIdx.x;
    if (e >= 6272) return;
    int c = e / 196, j = e - c * 196;
    int b = z / 96, tt = (z >> 3) % 12, h = z & 7;
    float v = part[(long)z * 6272 + e] + part[(long)(384 + z) * 6272 + e];
    g_mg[((long)b * 256 + h * 32 + c) * OBS_TOK + tt * 196 + j] = v;
}

__global__ void k_bnstats() {
    const int c = blockIdx.x;
    float s = 0.f, s2 = 0.f;
    for (int e = threadIdx.x; e < BB * THW; e += 256) {
        int b = e / THW, k = e - b * THW;
        float v = g_x[(long)b * CTHW + (long)c * THW + k];
        s += v; s2 += v * v;
    }
#pragma unroll
    for (int o = 16; o; o >>= 1) {
        s  += __shfl_xor_sync(0xffffffffu, s, o);
        s2 += __shfl_xor_sync(0xffffffffu, s2, o);
    }
    __shared__ float ws[8], ws2[8];
    int w = threadIdx.x >> 5;
    if ((threadIdx.x & 31) == 0) { ws[w] = s; ws2[w] = s2; }
    __syncthreads();
    if (threadIdx.x == 0) {
        float S = 0.f, S2 = 0.f;
#pragma unroll
        for (int i = 0; i < 8; i++) { S += ws[i]; S2 += ws2[i]; }
        float m = S * (1.f / 12544.f);
        float var = S2 * (1.f / 12544.f) - m * m;
        g_mean[c] = m;
        g_istd[c] = rsqrtf(var + EPSV);
    }
}

__global__ void k_bnapply(const float* __restrict__ gamma, const float* __restrict__ beta,
                          float* __restrict__ out) {
    int e = blockIdx.x * 256 + threadIdx.x;
    int c = (e / 784) & 255;
    float4 v = ((const float4*)g_x)[e];
    float a = gamma[c] * g_istd[c];
    float b2 = beta[c] - g_mean[c] * a;
    v.x = v.x * a + b2; v.y = v.y * a + b2; v.z = v.z * a + b2; v.w = v.w * a + b2;
    ((float4*)out)[e] = v;
}

extern "C" void kernel_launch(void* const* d_in, const int* in_sizes, int n_in,
                              void* d_out, int out_size) {
    const float* x    = (const float*)d_in[0];
    const float* w_dq = (const float*)d_in[1];
    const float* w_dk = (const float*)d_in[2];
    const float* w_dv = (const float*)d_in[3];
    const float* w_oq = (const float*)d_in[4];
    const float* w_ok = (const float*)d_in[5];
    const float* w_ov = (const float*)d_in[6];
    const float* w_oo = (const float*)d_in[7];
    const float* gam  = (const float*)d_in[8];
    const float* bet  = (const float*)d_in[9];
    float* out = (float*)d_out;

    float *p_x, *p_part;
    cudaGetSymbolAddress((void**)&p_x, g_x);
    cudaGetSymbolAddress((void**)&p_part, g_part);

    cudaFuncSetAttribute(k_obs_fused, cudaFuncAttributeMaxDynamicSharedMemorySize, 112640);
    cudaFuncSetAttribute(k_demo_fused, cudaFuncAttributeMaxDynamicSharedMemorySize, 59904);

    k_copy<<<3136, 256>>>((const float4*)x);

    for (int l = 0; l < 3; l++) {
        const int WO = l * 256 * 256;
        k_convD<<<dim3(13, 12, BB), 256>>>(w_dq + WO, w_dk + WO, w_dv + WO);
        k_convB<<<dim3(37, 12, BB), 256>>>(w_oq + WO, w_ok + WO, w_ov + WO);
        k_demo_fused<<<dim3(49, 32), 256, 59904>>>();
        k_obs_fused<<<dim3(384, 2), 256, 112640>>>(p_part);
        k_merge<<<dim3(25, 384), 256>>>(p_part);
        k_convO<<<dim3(37, 4, BB), 256>>>(w_oo + WO);
        k_bnstats<<<256, 256>>>();
        k_bnapply<<<3136, 256>>>(gam + l * 256, bet + l * 256, (l == 2) ? out : p_x);
    }
}